// round 4
// baseline (speedup 1.0000x reference)
#include <cuda_runtime.h>
#include <float.h>

// ParabolicPool2D: out[b,c,i,j] = max_{p,q in 0..2} f[b,c,2i+p,2j+q] + h[c,p,q]
// h[c,p,q] = -t[c]*(zp^2+zq^2)/2 -> separable with s = t[c]/2:
//   colmax[r][j] = max(f[r][2j]-s, f[r][2j+1], f[r][2j+2]-s)
//   out[i][j]    = max(colmax[2i]-s, colmax[2i+1], colmax[2i+2]-s)
//
// Lane L owns input cols [4L,4L+4) and [4L+128,4L+132): every LDG.128 is a
// contiguous 512B warp transaction. Neighbor element via __shfl.
// Software-pipelined: next iteration's 8 LDG.128 are issued between the
// colmax computation and the store phase, keeping loads continuously in flight.
// 32-output-row tiles cut seam re-reads to 1.2%.

#define Wd 256
#define Hd 256
#define OWd 127
#define OHd 127
#define Cd 128

struct Row { float4 a, b; };

__device__ __forceinline__ Row row_load(const float* __restrict__ row, int lane) {
    Row r;
    r.a = __ldcs((const float4*)(row + 4 * lane));
    r.b = __ldcs((const float4*)(row + 4 * lane + 128));
    return r;
}

__device__ __forceinline__ void row_cm(const Row& r, int lane, float s, float cm[4]) {
    float h0 = (lane == 0) ? r.b.x : r.a.x;
    int src = (lane + 1) & 31;
    float n0 = __shfl_sync(0xffffffffu, h0, src);      // col 4L+4 (lane31 <- lane0.b.x)
    float n1 = __shfl_sync(0xffffffffu, r.b.x, src);   // col 4L+132 (lane31: unused)
    cm[0] = fmaxf(fmaxf(r.a.x - s, r.a.y), r.a.z - s); // out col 2L
    cm[1] = fmaxf(fmaxf(r.a.z - s, r.a.w), n0 - s);    // out col 2L+1
    cm[2] = fmaxf(fmaxf(r.b.x - s, r.b.y), r.b.z - s); // out col 2L+64
    cm[3] = fmaxf(fmaxf(r.b.z - s, r.b.w), n1 - s);    // out col 2L+65
}

__device__ __forceinline__ void emit_row(float* __restrict__ orow, int j0,
                                         bool lastlane, float s,
                                         const float cmT[4], const float cmM[4],
                                         const float cmB[4]) {
    float o0 = fmaxf(fmaxf(cmT[0] - s, cmM[0]), cmB[0] - s);
    float o1 = fmaxf(fmaxf(cmT[1] - s, cmM[1]), cmB[1] - s);
    float o2 = fmaxf(fmaxf(cmT[2] - s, cmM[2]), cmB[2] - s);
    float o3 = fmaxf(fmaxf(cmT[3] - s, cmM[3]), cmB[3] - s);
    __stcs(orow + j0, o0);
    __stcs(orow + j0 + 1, o1);
    __stcs(orow + j0 + 64, o2);
    if (!lastlane) __stcs(orow + j0 + 65, o3);
}

__global__ void __launch_bounds__(256)
parabolic_pool2d_kernel(const float* __restrict__ f,
                        const float* __restrict__ t,
                        float* __restrict__ out) {
    int tid  = blockIdx.x * 256 + threadIdx.x;
    int lane = tid & 31;            // column owner within row
    int ti   = (tid >> 5) & 3;      // row tile: output rows [32*ti, 32*ti+32)
    int c    = (tid >> 7) & 127;
    int b    = tid >> 14;

    float s = 0.5f * __ldg(t + c);

    const float* fp = f + (size_t)(b * Cd + c) * (Hd * Wd);
    float*       op = out + (size_t)(b * Cd + c) * (OHd * OWd);

    int i0 = ti << 5;
    int r0 = i0 << 1;
    int j0 = 2 * lane;
    bool lastlane = (lane == 31);

    int imax = min(32, OHd - i0);   // 32, or 31 for the last tile
    int full = imax >> 1;           // 16 or 15 pair-iterations
    bool odd = (imax & 1) != 0;

    const float* rbase = fp + (size_t)r0 * Wd;

    float cmA[4];
    {
        Row A = row_load(rbase, lane);
        row_cm(A, lane, s, cmA);
    }
    // iteration k consumes input rows r0+4k+1 .. r0+4k+4
    Row B = row_load(rbase + 1 * Wd, lane);
    Row C = row_load(rbase + 2 * Wd, lane);
    Row D = row_load(rbase + 3 * Wd, lane);
    Row E = row_load(rbase + 4 * Wd, lane);

    for (int k = 0; k < full; k++) {
        float cmB[4], cmC[4], cmD[4], cmE[4];
        row_cm(B, lane, s, cmB);
        row_cm(C, lane, s, cmC);
        row_cm(D, lane, s, cmD);
        row_cm(E, lane, s, cmE);

        // prefetch next iteration's rows (warp-uniform branches)
        const float* rpn = rbase + (size_t)(4 * k + 5) * Wd;
        if (k + 1 < full) {
            B = row_load(rpn + 0 * Wd, lane);
            C = row_load(rpn + 1 * Wd, lane);
            D = row_load(rpn + 2 * Wd, lane);
            E = row_load(rpn + 3 * Wd, lane);
        } else if (odd) {           // tail needs rows r0+4k+5, r0+4k+6
            B = row_load(rpn + 0 * Wd, lane);
            C = row_load(rpn + 1 * Wd, lane);
        }

        float* orow = op + (size_t)(i0 + 2 * k) * OWd;
        emit_row(orow,       j0, lastlane, s, cmA, cmB, cmC);
        emit_row(orow + OWd, j0, lastlane, s, cmC, cmD, cmE);
#pragma unroll
        for (int u = 0; u < 4; u++) cmA[u] = cmE[u];
    }
    if (odd) {                      // one leftover output row
        float cmB[4], cmC[4];
        row_cm(B, lane, s, cmB);
        row_cm(C, lane, s, cmC);
        emit_row(op + (size_t)(i0 + imax - 1) * OWd, j0, lastlane, s, cmA, cmB, cmC);
    }
}

extern "C" void kernel_launch(void* const* d_in, const int* in_sizes, int n_in,
                              void* d_out, int out_size) {
    const float* f = (const float*)d_in[0];   // [16,128,256,256] fp32
    const float* t = (const float*)d_in[1];   // [128] fp32
    float* out = (float*)d_out;               // [16,128,127,127] fp32
    // threads = B(16) * C(128) * row_tiles(4) * lanes(32) = 262144 -> 1024 blocks
    parabolic_pool2d_kernel<<<1024, 256>>>(f, t, out);
}

// round 5
// speedup vs baseline: 1.0155x; 1.0155x over previous
#include <cuda_runtime.h>
#include <float.h>

// ParabolicPool2D: out[b,c,i,j] = max_{p,q in 0..2} f[b,c,2i+p,2j+q] + h[c,p,q]
// h[c,p,q] = -t[c]*(zp^2+zq^2)/2 -> separable with s = t[c]/2:
//   colmax[r][j] = max(f[r][2j]-s, f[r][2j+1], f[r][2j+2]-s)
//   out[i][j]    = max(colmax[2i]-s, colmax[2i+1], colmax[2i+2]-s)
//
// Persistent balanced decomposition: 152 SMs x 8 blocks x 4 warps = 4864 warps,
// all resident in wave 1 (no wave-quantization tail). The 2048x127 output rows
// are split into balanced contiguous per-warp ranges; vertical rolling reuse is
// kept within each run. Lane L owns input cols [4L,4L+4) and [4L+128,4L+132):
// every LDG.128 is a contiguous 512B warp transaction; neighbor via __shfl.

#define Wd 256
#define Hd 256
#define OWd 127
#define OHd 127
#define Cd 128

#define NBLOCKS 1216          // 152 SMs * 8 blocks
#define NWARPS  (NBLOCKS * 4) // 4864

struct Row { float4 a, b; };

__device__ __forceinline__ Row row_load(const float* __restrict__ row, int lane) {
    Row r;
    r.a = __ldcs((const float4*)(row + 4 * lane));
    r.b = __ldcs((const float4*)(row + 4 * lane + 128));
    return r;
}

__device__ __forceinline__ void row_cm(const Row& r, int lane, float s, float cm[4]) {
    float h0 = (lane == 0) ? r.b.x : r.a.x;
    int src = (lane + 1) & 31;
    float n0 = __shfl_sync(0xffffffffu, h0, src);      // col 4L+4 (lane31 <- lane0.b.x)
    float n1 = __shfl_sync(0xffffffffu, r.b.x, src);   // col 4L+132 (lane31: unused)
    cm[0] = fmaxf(fmaxf(r.a.x - s, r.a.y), r.a.z - s); // out col 2L
    cm[1] = fmaxf(fmaxf(r.a.z - s, r.a.w), n0 - s);    // out col 2L+1
    cm[2] = fmaxf(fmaxf(r.b.x - s, r.b.y), r.b.z - s); // out col 2L+64
    cm[3] = fmaxf(fmaxf(r.b.z - s, r.b.w), n1 - s);    // out col 2L+65
}

__device__ __forceinline__ void emit_row(float* __restrict__ orow, int j0,
                                         bool lastlane, float s,
                                         const float cmT[4], const float cmM[4],
                                         const float cmB[4]) {
    float o0 = fmaxf(fmaxf(cmT[0] - s, cmM[0]), cmB[0] - s);
    float o1 = fmaxf(fmaxf(cmT[1] - s, cmM[1]), cmB[1] - s);
    float o2 = fmaxf(fmaxf(cmT[2] - s, cmM[2]), cmB[2] - s);
    float o3 = fmaxf(fmaxf(cmT[3] - s, cmM[3]), cmB[3] - s);
    __stcs(orow + j0, o0);
    __stcs(orow + j0 + 1, o1);
    __stcs(orow + j0 + 64, o2);
    if (!lastlane) __stcs(orow + j0 + 65, o3);
}

__global__ void __launch_bounds__(128, 8)
parabolic_pool2d_kernel(const float* __restrict__ f,
                        const float* __restrict__ t,
                        float* __restrict__ out) {
    int w    = blockIdx.x * 4 + (threadIdx.x >> 5);  // global warp id, 0..NWARPS-1
    int lane = threadIdx.x & 31;
    int j0   = 2 * lane;
    bool lastlane = (lane == 31);

    const long TOTAL = 2048L * OHd;                  // 260096 output rows
    long g0 = ((long)w * TOTAL) / NWARPS;            // balanced contiguous range
    long g1 = ((long)(w + 1) * TOTAL) / NWARPS;

    while (g0 < g1) {
        int img = (int)(g0 / OHd);                   // image index = b*128 + c
        int i0  = (int)(g0 - (long)img * OHd);       // first output row in this run
        int n   = min(OHd - i0, (int)(g1 - g0));     // rows in this run

        const float* fp = f + (size_t)img * (Hd * Wd);
        float*       op = out + (size_t)img * (OHd * OWd);
        float s = 0.5f * __ldg(t + (img & (Cd - 1)));

        const float* rbase = fp + (size_t)(2 * i0) * Wd;
        float cmA[4];
        {
            Row A = row_load(rbase, lane);
            row_cm(A, lane, s, cmA);
        }

        int full = n >> 1;
        for (int k = 0; k < full; k++) {
            const float* rp = rbase + (size_t)(4 * k) * Wd;
            // ---- load phase: 8 back-to-back LDG.128 ----
            Row B = row_load(rp + 1 * Wd, lane);
            Row C = row_load(rp + 2 * Wd, lane);
            Row D = row_load(rp + 3 * Wd, lane);
            Row E = row_load(rp + 4 * Wd, lane);
            // ---- compute phase ----
            float cmB[4], cmC[4], cmD[4], cmE[4];
            row_cm(B, lane, s, cmB);
            row_cm(C, lane, s, cmC);
            row_cm(D, lane, s, cmD);
            row_cm(E, lane, s, cmE);

            float* orow = op + (size_t)(i0 + 2 * k) * OWd;
            emit_row(orow,       j0, lastlane, s, cmA, cmB, cmC);
            emit_row(orow + OWd, j0, lastlane, s, cmC, cmD, cmE);
#pragma unroll
            for (int u = 0; u < 4; u++) cmA[u] = cmE[u];
        }
        if (n & 1) {                                 // one leftover output row
            const float* rp = rbase + (size_t)(4 * full) * Wd;
            Row B = row_load(rp + 1 * Wd, lane);
            Row C = row_load(rp + 2 * Wd, lane);
            float cmB[4], cmC[4];
            row_cm(B, lane, s, cmB);
            row_cm(C, lane, s, cmC);
            emit_row(op + (size_t)(i0 + n - 1) * OWd, j0, lastlane, s, cmA, cmB, cmC);
        }
        g0 += n;
    }
}

extern "C" void kernel_launch(void* const* d_in, const int* in_sizes, int n_in,
                              void* d_out, int out_size) {
    const float* f = (const float*)d_in[0];   // [16,128,256,256] fp32
    const float* t = (const float*)d_in[1];   // [128] fp32
    float* out = (float*)d_out;               // [16,128,127,127] fp32
    parabolic_pool2d_kernel<<<NBLOCKS, 128>>>(f, t, out);
}

// round 6
// speedup vs baseline: 1.1015x; 1.0847x over previous
#include <cuda_runtime.h>
#include <cstdint>

// ParabolicPool2D: out[b,c,i,j] = max_{p,q in 0..2} f[b,c,2i+p,2j+q] + h[c,p,q]
// h[c,p,q] = -t[c]*(zp^2+zq^2)/2 -> separable with s = t[c]/2:
//   colmax[r][j] = max(f[r][2j]-s, f[r][2j+1], f[r][2j+2]-s)
//   out[i][j]    = max(colmax[2i]-s, colmax[2i+1], colmax[2i+2]-s)
//
// Block-cooperative: each block = one (image, 16-output-row tile). One
// cp.async.bulk of 33KB (33 input rows) into smem -> long sequential DRAM
// bursts (row-buffer friendly) instead of thousands of interleaved 512B
// streams. Compute reads smem directly (neighbor element via scalar LDS,
// no shuffles). 8 warps x 2 output rows.

#define Wd 256
#define OWd 127
#define OHd 127

__device__ __forceinline__ uint32_t smem_u32(const void* p) {
    return (uint32_t)__cvta_generic_to_shared(p);
}

__device__ __forceinline__ void cm_row(const float* __restrict__ sr, int lane,
                                       float s, float cm[4]) {
    float4 a = *(const float4*)(sr + 4 * lane);
    float4 b = *(const float4*)(sr + 4 * lane + 128);
    float n0 = sr[4 * lane + 4];                       // col 4L+4
    float n1 = sr[(lane == 31) ? 255 : (4 * lane + 132)]; // col 4L+132 (lane31 unused)
    cm[0] = fmaxf(fmaxf(a.x - s, a.y), a.z - s);       // out col 2L
    cm[1] = fmaxf(fmaxf(a.z - s, a.w), n0 - s);        // out col 2L+1
    cm[2] = fmaxf(fmaxf(b.x - s, b.y), b.z - s);       // out col 2L+64
    cm[3] = fmaxf(fmaxf(b.z - s, b.w), n1 - s);        // out col 2L+65
}

__global__ void __launch_bounds__(256)
parabolic_pool2d_kernel(const float* __restrict__ f,
                        const float* __restrict__ t,
                        float* __restrict__ out) {
    __shared__ __align__(128) float sm[33 * Wd];       // 33 input rows
    __shared__ __align__(8) unsigned long long mbar;

    int bid  = blockIdx.x;
    int img  = bid >> 3;                 // image = b*128 + c
    int tile = bid & 7;                  // 16-output-row tile within image
    int i0 = tile << 4;
    int nout = min(16, OHd - i0);        // 16, or 15 for tile 7
    int nin  = 2 * nout + 1;             // 33 or 31 input rows
    int bytes = nin * (Wd * 4);          // 33792 or 31744 (16B multiple)

    const float* src = f + (size_t)img * (256 * Wd) + (size_t)(i0 << 1) * Wd;

    uint32_t sm_a = smem_u32(sm);
    uint32_t mb_a = smem_u32(&mbar);

    if (threadIdx.x == 0) {
        asm volatile("mbarrier.init.shared.b64 [%0], 1;" :: "r"(mb_a) : "memory");
    }
    __syncthreads();
    if (threadIdx.x == 0) {
        asm volatile("mbarrier.arrive.expect_tx.shared.b64 _, [%0], %1;"
                     :: "r"(mb_a), "r"(bytes) : "memory");
        asm volatile("cp.async.bulk.shared::cta.global.mbarrier::complete_tx::bytes"
                     " [%0], [%1], %2, [%3];"
                     :: "r"(sm_a), "l"(src), "r"(bytes), "r"(mb_a) : "memory");
    }

    float s = 0.5f * __ldg(t + (img & 127));
    float* op = out + (size_t)img * (OHd * OWd);
    int w    = threadIdx.x >> 5;
    int lane = threadIdx.x & 31;
    int j0   = 2 * lane;
    bool lastlane = (lane == 31);

    // wait for bulk copy (parity 0, first and only phase this block uses)
    {
        uint32_t done;
        asm volatile(
            "{\n\t.reg .pred p;\n\t"
            "mbarrier.try_wait.parity.acquire.cta.shared::cta.b64 p, [%1], 0;\n\t"
            "selp.b32 %0, 1, 0, p;\n\t}"
            : "=r"(done) : "r"(mb_a) : "memory");
        if (!done) {
            asm volatile(
                "{\n\t.reg .pred P1;\n\t"
                "W1_%=:\n\t"
                "mbarrier.try_wait.parity.acquire.cta.shared::cta.b64 P1, [%0], 0, 0x989680;\n\t"
                "@P1 bra.uni D1_%=;\n\t"
                "bra.uni W1_%=;\n\t"
                "D1_%=:\n\t}"
                :: "r"(mb_a) : "memory");
        }
    }

    // warp w computes output rows i0+w and i0+w+8
#pragma unroll
    for (int half = 0; half < 2; half++) {
        int i = w + 8 * half;            // local output row 0..15
        if (i < nout) {
            const float* r0p = sm + (size_t)(2 * i) * Wd;
            float cmA[4], cmB[4], cmC[4];
            cm_row(r0p,          lane, s, cmA);
            cm_row(r0p + Wd,     lane, s, cmB);
            cm_row(r0p + 2 * Wd, lane, s, cmC);

            float o0 = fmaxf(fmaxf(cmA[0] - s, cmB[0]), cmC[0] - s);
            float o1 = fmaxf(fmaxf(cmA[1] - s, cmB[1]), cmC[1] - s);
            float o2 = fmaxf(fmaxf(cmA[2] - s, cmB[2]), cmC[2] - s);
            float o3 = fmaxf(fmaxf(cmA[3] - s, cmB[3]), cmC[3] - s);

            float* orow = op + (size_t)(i0 + i) * OWd;
            __stcs(orow + j0, o0);
            __stcs(orow + j0 + 1, o1);
            __stcs(orow + j0 + 64, o2);
            if (!lastlane) __stcs(orow + j0 + 65, o3);
        }
    }
}

extern "C" void kernel_launch(void* const* d_in, const int* in_sizes, int n_in,
                              void* d_out, int out_size) {
    const float* f = (const float*)d_in[0];   // [16,128,256,256] fp32
    const float* t = (const float*)d_in[1];   // [128] fp32
    float* out = (float*)d_out;               // [16,128,127,127] fp32
    // 2048 images * 8 tiles = 16384 blocks, 256 threads each
    parabolic_pool2d_kernel<<<16384, 256>>>(f, t, out);
}